// round 11
// baseline (speedup 1.0000x reference)
#include <cuda_runtime.h>
#include <math.h>

#define B_    32
#define TENC  200
#define E_    512
#define D_    1024
#define P_    256
#define M_    80
#define TDEC  600
#define A_    128
#define LF_   32
#define KW_   31
#define PADW  15
#define NBLK  128
#define NTHR  512
#define CHUNK 128
#define WPAD  132                 // padded chunk stride in floats (528B, 16B-aligned)
#define BUFFL (2 * 32 * WPAD)     // floats per (w,x) buffer = 8448
#define REDOFF (3 * BUFFL)        // 25344
#define POOLFL (REDOFF + 16896)   // + red [16][32*33] = 42240 floats = 168960 B

// ---------------- device scratch (static, allocation-free) ----------------
__device__ __align__(16) float g_pre[(size_t)B_ * TDEC * P_];
__device__ __align__(16) float g_pm[(size_t)B_ * TENC * A_];
__device__ __align__(16) float g_lp[(size_t)B_ * TENC * A_];
__device__ __align__(16) float g_hatt[B_ * D_];
__device__ __align__(16) float g_catt[B_ * D_];
__device__ __align__(16) float g_hgen[B_ * D_];
__device__ __align__(16) float g_cgen[B_ * D_];
__device__ __align__(16) float g_ctx[2][B_ * E_];
__device__ __align__(16) float g_wprev[B_ * TENC];
__device__ __align__(16) float g_wcum[B_ * TENC];
__device__ __align__(16) float g_gatt[(size_t)B_ * 4 * D_];
__device__ __align__(16) float g_ggen[(size_t)B_ * 4 * D_];

// ---------------- grid barrier ----------------
__device__ unsigned g_count = 0;
__device__ volatile unsigned g_sense = 0;

__device__ __forceinline__ void grid_bar(unsigned& ls) {
    __syncthreads();
    ls ^= 1u;
    if (threadIdx.x == 0) {
        __threadfence();
        unsigned old = atomicAdd(&g_count, 1u);
        if (old == NBLK - 1) {
            atomicExch(&g_count, 0u);
            __threadfence();
            g_sense = ls;
        } else {
            while (g_sense != ls) { __nanosleep(32); }
            __threadfence();
        }
    }
    __syncthreads();
}

// ---------------- helpers ----------------
__device__ __forceinline__ float warp_sum(float v) {
    v += __shfl_xor_sync(0xffffffffu, v, 16);
    v += __shfl_xor_sync(0xffffffffu, v, 8);
    v += __shfl_xor_sync(0xffffffffu, v, 4);
    v += __shfl_xor_sync(0xffffffffu, v, 2);
    v += __shfl_xor_sync(0xffffffffu, v, 1);
    return v;
}
__device__ __forceinline__ float warp_max(float v) {
    v = fmaxf(v, __shfl_xor_sync(0xffffffffu, v, 16));
    v = fmaxf(v, __shfl_xor_sync(0xffffffffu, v, 8));
    v = fmaxf(v, __shfl_xor_sync(0xffffffffu, v, 4));
    v = fmaxf(v, __shfl_xor_sync(0xffffffffu, v, 2));
    v = fmaxf(v, __shfl_xor_sync(0xffffffffu, v, 1));
    return v;
}
__device__ __forceinline__ float sigf(float x) { return 1.f / (1.f + __expf(-x)); }

typedef unsigned long long ull;
__device__ __forceinline__ ull pk(float lo, float hi) {
    ull r; asm("mov.b64 %0, {%1, %2};" : "=l"(r) : "f"(lo), "f"(hi)); return r;
}
__device__ __forceinline__ float2 upk(ull v) {
    float2 f; asm("mov.b64 {%0, %1}, %2;" : "=f"(f.x), "=f"(f.y) : "l"(v)); return f;
}
__device__ __forceinline__ void fma2(ull& acc, ull a, ull b) {
    asm("fma.rn.f32x2 %0, %1, %2, %0;" : "+l"(acc) : "l"(a), "l"(b));
}
__device__ __forceinline__ void lds_2x64(ull& a, ull& b, unsigned saddr) {
    asm volatile("ld.shared.v2.b64 {%0, %1}, [%2];" : "=l"(a), "=l"(b) : "r"(saddr));
}
__device__ __forceinline__ unsigned sptr(const void* p) {
    return (unsigned)__cvta_generic_to_shared(p);
}
__device__ __forceinline__ void cp16(float* smem_dst, const float* gsrc) {
    unsigned s = (unsigned)__cvta_generic_to_shared(smem_dst);
    asm volatile("cp.async.cg.shared.global [%0], [%1], 16;" :: "r"(s), "l"(gsrc));
}
__device__ __forceinline__ void cp_commit() { asm volatile("cp.async.commit_group;"); }
__device__ __forceinline__ void cp_wait1() { asm volatile("cp.async.wait_group 1;"); }
__device__ __forceinline__ void cp_wait0() { asm volatile("cp.async.wait_group 0;"); }

// ---------------- LSTM gate GEMM: gates[b][4096 rows] ----------------
// Block = 32 rows x 32 b. Thread tile 8 rows x 4 b, k-split 16.
// Triple-buffered cp.async staging (one sync per chunk), FFMA2 inner.
__device__ void lstm_gates(const float* __restrict__ Wih, const float* __restrict__ Whh,
                           int KX,
                           const float* s0, int l0, int st0,
                           const float* s1, int l1, int st1,
                           const float* s2, int st2,
                           float* __restrict__ gates_out, float* pool, int blk) {
    const int KTOT = KX + D_;
    const int NCH = KTOT / CHUNK;
    const int rowbase = blk * 32;
    const int tid = threadIdx.x;
    const int bg = tid & 7;            // batch group: b = bg + 8j
    const int rg = (tid >> 3) & 3;     // row group:   r = rg + 4i
    const int kg = tid >> 5;           // 0..15: k-quantum of 8 floats

    const unsigned pool_sa = sptr(pool);
    float* red = pool + REDOFF;

    const int i0 = tid, i1 = tid + NTHR;
    const int wr0 = i0 >> 5, wc0 = (i0 & 31) * 4;
    const int wr1 = i1 >> 5, wc1 = (i1 & 31) * 4;

    #define STAGE(buf_, tb_)  do {                                               \
        int tb = (tb_);                                                           \
        float* wb = pool + (buf_) * BUFFL;                                         \
        float* xb = wb + 32 * WPAD;                                                \
        {                                                                          \
            int k = tb + wc0;                                                      \
            const float* src = (k < KX) ? Wih + (size_t)(rowbase + wr0) * KX + k   \
                                        : Whh + (size_t)(rowbase + wr0) * D_ + (k - KX); \
            cp16(wb + wr0 * WPAD + wc0, src);                                      \
        }                                                                          \
        {                                                                          \
            int k = tb + wc1;                                                      \
            const float* src = (k < KX) ? Wih + (size_t)(rowbase + wr1) * KX + k   \
                                        : Whh + (size_t)(rowbase + wr1) * D_ + (k - KX); \
            cp16(wb + wr1 * WPAD + wc1, src);                                      \
        }                                                                          \
        {                                                                          \
            int k = tb + wc0;                                                      \
            const float* src;                                                      \
            if (k < l0)           src = s0 + (size_t)wr0 * st0 + k;                \
            else if (k < l0 + l1) src = s1 + (size_t)wr0 * st1 + (k - l0);         \
            else                  src = s2 + (size_t)wr0 * st2 + (k - l0 - l1);    \
            cp16(xb + wr0 * WPAD + wc0, src);                                      \
        }                                                                          \
        {                                                                          \
            int k = tb + wc1;                                                      \
            const float* src;                                                      \
            if (k < l0)           src = s0 + (size_t)wr1 * st0 + k;                \
            else if (k < l0 + l1) src = s1 + (size_t)wr1 * st1 + (k - l0);         \
            else                  src = s2 + (size_t)wr1 * st2 + (k - l0 - l1);    \
            cp16(xb + wr1 * WPAD + wc1, src);                                      \
        }                                                                          \
    } while (0)

    ull acc[8][4];
    #pragma unroll
    for (int i = 0; i < 8; i++)
        #pragma unroll
        for (int j = 0; j < 4; j++) acc[i][j] = 0ull;

    STAGE(0, 0); cp_commit();
    STAGE(1, CHUNK); cp_commit();

    int bi = 0, si = 2;
    for (int c = 0; c < NCH; c++) {
        if (c + 1 < NCH) cp_wait1(); else cp_wait0();
        __syncthreads();
        if (c + 2 < NCH) { STAGE(si, (c + 2) * CHUNK); cp_commit(); }

        const unsigned wbase = pool_sa + (unsigned)(bi * BUFFL + rg * WPAD + kg * 8) * 4u;
        const unsigned xbase = pool_sa + (unsigned)(bi * BUFFL + 32 * WPAD + bg * WPAD + kg * 8) * 4u;
        #pragma unroll
        for (int q = 0; q < 2; q++) {
            ull x[8];
            lds_2x64(x[0], x[1], xbase + q * 16);
            lds_2x64(x[2], x[3], xbase + 8 * WPAD * 4 + q * 16);
            lds_2x64(x[4], x[5], xbase + 16 * WPAD * 4 + q * 16);
            lds_2x64(x[6], x[7], xbase + 24 * WPAD * 4 + q * 16);
            #pragma unroll
            for (int half = 0; half < 2; half++) {
                ull w[8];
                lds_2x64(w[0], w[1], wbase + (16 * half + 0) * WPAD * 4 + q * 16);
                lds_2x64(w[2], w[3], wbase + (16 * half + 4) * WPAD * 4 + q * 16);
                lds_2x64(w[4], w[5], wbase + (16 * half + 8) * WPAD * 4 + q * 16);
                lds_2x64(w[6], w[7], wbase + (16 * half + 12) * WPAD * 4 + q * 16);
                #pragma unroll
                for (int ii = 0; ii < 4; ii++)
                    #pragma unroll
                    for (int j = 0; j < 4; j++) {
                        fma2(acc[4 * half + ii][j], w[2 * ii],     x[2 * j]);
                        fma2(acc[4 * half + ii][j], w[2 * ii + 1], x[2 * j + 1]);
                    }
            }
        }
        bi = (bi == 2) ? 0 : bi + 1;
        si = (si == 2) ? 0 : si + 1;
    }
    #undef STAGE

    __syncthreads();
    #pragma unroll
    for (int i = 0; i < 8; i++)
        #pragma unroll
        for (int j = 0; j < 4; j++) {
            float2 f = upk(acc[i][j]);
            red[kg * (32 * 33) + (rg + 4 * i) * 33 + (bg + 8 * j)] = f.x + f.y;
        }
    __syncthreads();
    for (int p = tid; p < 1024; p += NTHR) {
        int b = p >> 5, r = p & 31;
        float s = 0.f;
        #pragma unroll
        for (int q = 0; q < 16; q++) s += red[q * (32 * 33) + r * 33 + b];
        gates_out[(size_t)b * (4 * D_) + rowbase + r] = s;
    }
    __syncthreads();
}

// ---------------- B1 (blocks 0-31): att pointwise + query ----------------
__device__ void att_pw_query(int b, float* pool,
                             const float* __restrict__ ab,
                             const float* __restrict__ Wq,
                             const float* __restrict__ b_att,
                             const float* __restrict__ v_att) {
    const int tid = threadIdx.x;
    const int warp = tid >> 5, lane = tid & 31;
    float* h_s = pool;           // 1024
    float* q_s = pool + 1024;    // 128
    float* v_s = pool + 1152;    // 128

    const float* gat = g_gatt + (size_t)b * (4 * D_);
    for (int d = tid; d < D_; d += NTHR) {
        float gi = gat[d]          + ab[d];
        float gf = gat[D_ + d]     + ab[D_ + d];
        float gc = gat[2 * D_ + d] + ab[2 * D_ + d];
        float go = gat[3 * D_ + d] + ab[3 * D_ + d];
        float c = sigf(gf) * g_catt[b * D_ + d] + sigf(gi) * tanhf(gc);
        float h = sigf(go) * tanhf(c);
        g_catt[b * D_ + d] = c;
        g_hatt[b * D_ + d] = h;
        h_s[d] = h;
    }
    if (tid < A_) v_s[tid] = v_att[tid];
    __syncthreads();

    const float4* h4 = (const float4*)h_s;
    for (int a = warp * 8; a < warp * 8 + 8; a++) {
        const float4* wq = (const float4*)(Wq + (size_t)a * D_);
        float acc = 0.f;
        #pragma unroll
        for (int kk = 0; kk < 8; kk++) {
            float4 w4 = wq[lane + 32 * kk];
            float4 x4 = h4[lane + 32 * kk];
            acc += w4.x * x4.x + w4.y * x4.y + w4.z * x4.z + w4.w * x4.w;
        }
        acc = warp_sum(acc);
        if (lane == 0) q_s[a] = acc + b_att[a];
    }
    __syncthreads();
}

// ---------------- B1 (blocks 32-127): conv + locproj for (b, third) ----------------
__device__ void conv_locproj(int b, int third, float* pool,
                             const float* __restrict__ lk,
                             const float* __restrict__ Wloc) {
    const int tid = threadIdx.x;
    const int lo = third * 67;
    const int n = (third == 2) ? 66 : 67;

    float* wp_s  = pool;          // 104
    float* wc_s  = pool + 104;    // 104
    float* lkT   = pool + 208;    // 62*33
    float* wlocT = pool + 2256;   // 32*129
    float* feat  = pool + 6400;   // 67*36

    for (int idx = tid; idx < 104; idx += NTHR) {
        int j = lo - 15 + idx;
        bool ok = (j >= 0 && j < TENC);
        wp_s[idx] = ok ? g_wprev[b * TENC + j] : 0.f;
        wc_s[idx] = ok ? g_wcum[b * TENC + j] : 0.f;
    }
    for (int idx = tid; idx < 62 * 32; idx += NTHR) {
        int tap = idx >> 5, c = idx & 31;
        lkT[tap * 33 + c] = lk[c * 62 + tap];
    }
    for (int idx = tid; idx < A_ * LF_; idx += NTHR) {
        int a = idx >> 5, c = idx & 31;
        wlocT[c * 129 + a] = Wloc[idx];
    }
    __syncthreads();

    {
        int c = tid & 31, iq = tid >> 5;
        for (int p = 0; p < 2; p++) {
            int ig4 = p * 64 + iq * 4;
            if (ig4 < n) {
                float f0 = 0.f, f1 = 0.f, f2 = 0.f, f3 = 0.f;
                {
                    float a0 = wp_s[ig4], a1 = wp_s[ig4 + 1], a2 = wp_s[ig4 + 2], a3 = wp_s[ig4 + 3];
                    #pragma unroll
                    for (int k = 0; k < KW_; k++) {
                        float lkv = lkT[k * 33 + c];
                        f0 += lkv * a0; f1 += lkv * a1; f2 += lkv * a2; f3 += lkv * a3;
                        a0 = a1; a1 = a2; a2 = a3; a3 = wp_s[ig4 + k + 4];
                    }
                }
                {
                    float a0 = wc_s[ig4], a1 = wc_s[ig4 + 1], a2 = wc_s[ig4 + 2], a3 = wc_s[ig4 + 3];
                    #pragma unroll
                    for (int k = 0; k < KW_; k++) {
                        float lkv = lkT[(KW_ + k) * 33 + c];
                        f0 += lkv * a0; f1 += lkv * a1; f2 += lkv * a2; f3 += lkv * a3;
                        a0 = a1; a1 = a2; a2 = a3; a3 = wc_s[ig4 + k + 4];
                    }
                }
                if (ig4 + 0 < n) feat[(ig4 + 0) * 36 + c] = f0;
                if (ig4 + 1 < n) feat[(ig4 + 1) * 36 + c] = f1;
                if (ig4 + 2 < n) feat[(ig4 + 2) * 36 + c] = f2;
                if (ig4 + 3 < n) feat[(ig4 + 3) * 36 + c] = f3;
            }
        }
    }
    __syncthreads();

    {
        int a = tid & 127, ig2 = tid >> 7;
        ull wl[16];
        #pragma unroll
        for (int p4 = 0; p4 < 8; p4++) {
            wl[2 * p4]     = pk(wlocT[(4 * p4) * 129 + a],     wlocT[(4 * p4 + 1) * 129 + a]);
            wl[2 * p4 + 1] = pk(wlocT[(4 * p4 + 2) * 129 + a], wlocT[(4 * p4 + 3) * 129 + a]);
        }
        unsigned feat_sa = sptr(feat);
        for (int ii = ig2; ii < n; ii += 4) {
            ull acc = 0ull;
            unsigned base = feat_sa + (unsigned)ii * 144u;
            #pragma unroll
            for (int p4 = 0; p4 < 8; p4++) {
                ull f0, f1;
                lds_2x64(f0, f1, base + p4 * 16);
                fma2(acc, wl[2 * p4], f0);
                fma2(acc, wl[2 * p4 + 1], f1);
            }
            float2 f = upk(acc);
            g_lp[((size_t)b * TENC + lo + ii) * A_ + a] = f.x + f.y;
        }
    }
    __syncthreads();
}

// ---------------- B2 (blocks 0-31): energy + softmax + context ----------------
__device__ void energy_softmax_ctx(int b, int t, float* pool,
                                   const int* __restrict__ lens,
                                   const float* __restrict__ enc,
                                   float* __restrict__ align_out) {
    const int tid = threadIdx.x;
    const int warp = tid >> 5, lane = tid & 31;
    float* q_s   = pool + 1024;
    float* v_s   = pool + 1152;
    float* e_s   = pool + 1280;
    float* red16 = pool + 1504;
    float* cpart = pool + 1536;

    int len = lens[b];
    for (int i = warp; i < TENC; i += 16) {
        const float* lp = g_lp + ((size_t)b * TENC + i) * A_;
        const float* pm = g_pm + ((size_t)b * TENC + i) * A_;
        float part = 0.f;
        #pragma unroll
        for (int aa = 0; aa < 4; aa++) {
            int a = aa * 32 + lane;
            part += tanhf(q_s[a] + pm[a] + lp[a]) * v_s[a];
        }
        part = warp_sum(part);
        if (lane == 0) e_s[i] = (i < len) ? part : -1e9f;
    }
    __syncthreads();

    float e = (tid < TENC) ? e_s[tid] : -1e30f;
    float m = warp_max(e);
    if (lane == 0) red16[warp] = m;
    __syncthreads();
    if (tid == 0) {
        float mm = red16[0];
        #pragma unroll
        for (int i = 1; i < 16; i++) mm = fmaxf(mm, red16[i]);
        red16[0] = mm;
    }
    __syncthreads();
    float mx = red16[0];
    __syncthreads();
    float ex = (tid < TENC) ? __expf(e - mx) : 0.f;
    float ssum = warp_sum(ex);
    if (lane == 0) red16[warp] = ssum;
    __syncthreads();
    if (tid == 0) {
        float tot = 0.f;
        #pragma unroll
        for (int i = 0; i < 16; i++) tot += red16[i];
        red16[0] = tot;
    }
    __syncthreads();
    float inv = 1.f / red16[0];
    if (tid < TENC) {
        float w = ex * inv;
        e_s[tid] = w;
        g_wprev[b * TENC + tid] = w;
        g_wcum[b * TENC + tid] += w;
        align_out[((size_t)b * TDEC + t) * TENC + tid] = w;
    }
    __syncthreads();

    if (tid < 256) {
        int col = tid & 127, half = tid >> 7;
        const float4* encb = (const float4*)(enc + (size_t)b * TENC * E_) + col;
        float4 acc = make_float4(0.f, 0.f, 0.f, 0.f);
        #pragma unroll 4
        for (int i = half * 100; i < half * 100 + 100; i++) {
            float w = e_s[i];
            float4 v = encb[(size_t)i * 128];
            acc.x += w * v.x; acc.y += w * v.y; acc.z += w * v.z; acc.w += w * v.w;
        }
        ((float4*)cpart)[tid] = acc;
    }
    __syncthreads();
    if (tid < 128) {
        float4 a0 = ((float4*)cpart)[tid];
        float4 a1 = ((float4*)cpart)[tid + 128];
        float4 r = make_float4(a0.x + a1.x, a0.y + a1.y, a0.z + a1.z, a0.w + a1.w);
        ((float4*)(g_ctx[t & 1] + b * E_))[tid] = r;
    }
    __syncthreads();
}

// ---------------- gen pointwise + frame/stop for step tt ----------------
__device__ void genpw_frame(int b, int tt, float* pool,
                            const float* __restrict__ gb,
                            const float* __restrict__ fW, const float* __restrict__ fb,
                            const float* __restrict__ sW, const float* __restrict__ sb,
                            float* __restrict__ spec, float* __restrict__ stop) {
    const int tid = threadIdx.x;
    const int warp = tid >> 5, lane = tid & 31;
    float* proto = pool;

    const float* gg = g_ggen + (size_t)b * (4 * D_);
    for (int d = tid; d < D_; d += NTHR) {
        float gi = gg[d]          + gb[d];
        float gf = gg[D_ + d]     + gb[D_ + d];
        float gc = gg[2 * D_ + d] + gb[2 * D_ + d];
        float go = gg[3 * D_ + d] + gb[3 * D_ + d];
        float c = sigf(gf) * g_cgen[b * D_ + d] + sigf(gi) * tanhf(gc);
        float h = sigf(go) * tanhf(c);
        g_cgen[b * D_ + d] = c;
        g_hgen[b * D_ + d] = h;
        proto[d] = h;
    }
    const float* cx = g_ctx[tt & 1] + b * E_;
    for (int k = tid; k < E_; k += NTHR) proto[D_ + k] = cx[k];
    __syncthreads();

    for (int r = warp; r < M_ + 1; r += 16) {
        const float* w = (r < M_) ? (fW + (size_t)r * (D_ + E_)) : sW;
        float acc = 0.f;
        for (int k = lane * 4; k < D_ + E_; k += 128) {
            float4 w4 = *(const float4*)(w + k);
            float4 x4 = *(const float4*)(proto + k);
            acc += w4.x * x4.x + w4.y * x4.y + w4.z * x4.z + w4.w * x4.w;
        }
        acc = warp_sum(acc);
        if (lane == 0) {
            if (r < M_) spec[((size_t)b * TDEC + tt) * M_ + r] = acc + fb[r];
            else        stop[(size_t)b * TDEC + tt] = acc + sb[0];
        }
    }
    __syncthreads();
}

// ---------------- the persistent decoder ----------------
__global__ void __launch_bounds__(NTHR, 1)
decoder_kernel(const float* __restrict__ enc, const int* __restrict__ lens,
               const float* __restrict__ aWih, const float* __restrict__ aWhh, const float* __restrict__ ab,
               const float* __restrict__ gWih, const float* __restrict__ gWhh, const float* __restrict__ gb,
               const float* __restrict__ Wq, const float* __restrict__ lk,
               const float* __restrict__ Wloc, const float* __restrict__ v_att, const float* __restrict__ b_att,
               const float* __restrict__ fW, const float* __restrict__ fb,
               const float* __restrict__ sW, const float* __restrict__ sb,
               float* __restrict__ spec, float* __restrict__ stop, float* __restrict__ align_out) {
    extern __shared__ __align__(16) float pool[];
    const int blk = blockIdx.x;
    unsigned ls = g_sense;

    for (int t = 0; t < TDEC; t++) {
        // Phase A: att-LSTM gates. x = [pre_t | ctx_{t-1}], h = h_att^{t-1}
        lstm_gates(aWih, aWhh, P_ + E_,
                   g_pre + (size_t)t * P_, P_, TDEC * P_,
                   g_ctx[(t + 1) & 1], E_, E_,
                   g_hatt, D_,
                   g_gatt, pool, blk);
        grid_bar(ls);
        // Phase B1: pointwise+query (0-31) || conv+locproj (32-127)
        if (blk < 32) {
            att_pw_query(blk, pool, ab, Wq, b_att, v_att);
        } else {
            int cb = blk - 32;
            conv_locproj(cb & 31, cb >> 5, pool, lk, Wloc);
        }
        grid_bar(ls);
        // Phase B2: energy/softmax/context (0-31) || frame of t-1 (32-63)
        if (blk < 32) {
            energy_softmax_ctx(blk, t, pool, lens, enc, align_out);
        } else if (blk < 64 && t > 0) {
            genpw_frame(blk - 32, t - 1, pool, gb, fW, fb, sW, sb, spec, stop);
        }
        grid_bar(ls);
        // Phase C: gen-LSTM gates. x = [h_att | ctx_t], h = h_gen^{t-1}
        lstm_gates(gWih, gWhh, D_ + E_,
                   g_hatt, D_, D_,
                   g_ctx[t & 1], E_, E_,
                   g_hgen, D_,
                   g_ggen, pool, blk);
    }
    grid_bar(ls);
    if (blk >= 32 && blk < 64) {
        genpw_frame(blk - 32, TDEC - 1, pool, gb, fW, fb, sW, sb, spec, stop);
    }
}

// ---------------- prologue kernels ----------------
__global__ void init_kernel() {
    int i = blockIdx.x * blockDim.x + threadIdx.x;
    if (i < B_ * D_) { g_hatt[i] = 0.f; g_catt[i] = 0.f; g_hgen[i] = 0.f; g_cgen[i] = 0.f; }
    if (i < B_ * E_) { g_ctx[0][i] = 0.f; g_ctx[1][i] = 0.f; }
    if (i < B_ * TENC) { g_wprev[i] = 0.f; g_wcum[i] = 0.f; }
}

__global__ void prenet_kernel(const float* __restrict__ target,
                              const float* __restrict__ W1, const float* __restrict__ b1,
                              const float* __restrict__ W2, const float* __restrict__ b2) {
    int bt = blockIdx.x;
    int b = bt / TDEC, t = bt % TDEC;
    __shared__ float st[M_];
    __shared__ float sx1[P_];
    int tid = threadIdx.x;  // 256
    int warp = tid >> 5, lane = tid & 31;
    if (tid < M_) st[tid] = (t == 0) ? 0.f : target[((size_t)b * M_ + tid) * TDEC + (t - 1)];
    __syncthreads();
    for (int j = 0; j < 32; j++) {
        int p = warp * 32 + j;
        const float* w = W1 + (size_t)p * M_;
        float acc = w[lane] * st[lane] + w[lane + 32] * st[lane + 32];
        if (lane < 16) acc += w[lane + 64] * st[lane + 64];
        acc = warp_sum(acc);
        if (lane == 0) sx1[p] = fmaxf(acc + b1[p], 0.f);
    }
    __syncthreads();
    for (int j = 0; j < 32; j++) {
        int p = warp * 32 + j;
        const float* w = W2 + (size_t)p * P_;
        float acc = 0.f;
        #pragma unroll
        for (int q = 0; q < 8; q++) acc += w[lane + 32 * q] * sx1[lane + 32 * q];
        acc = warp_sum(acc);
        if (lane == 0) g_pre[((size_t)b * TDEC + t) * P_ + p] = fmaxf(acc + b2[p], 0.f);
    }
}

__global__ void procmem_kernel(const float* __restrict__ enc, const float* __restrict__ Wm) {
    int i = blockIdx.x, b = blockIdx.y;
    __shared__ __align__(16) float se[E_];
    int tid = threadIdx.x;  // 128
    int warp = tid >> 5, lane = tid & 31;
    for (int k = tid; k < E_; k += 128) se[k] = enc[((size_t)b * TENC + i) * E_ + k];
    __syncthreads();
    const float4* se4 = (const float4*)se;
    for (int j = 0; j < 32; j++) {
        int a = warp * 32 + j;
        const float4* w4 = (const float4*)(Wm + (size_t)a * E_);
        float acc = 0.f;
        #pragma unroll
        for (int q = 0; q < 4; q++) {
            float4 w = w4[lane + 32 * q];
            float4 x = se4[lane + 32 * q];
            acc += w.x * x.x + w.y * x.y + w.z * x.z + w.w * x.w;
        }
        acc = warp_sum(acc);
        if (lane == 0) g_pm[((size_t)b * TENC + i) * A_ + a] = acc;
    }
}

// ---------------- launch ----------------
extern "C" void kernel_launch(void* const* d_in, const int* in_sizes, int n_in,
                              void* d_out, int out_size) {
    const float* enc    = (const float*)d_in[0];
    const int*   lens   = (const int*)d_in[1];
    const float* target = (const float*)d_in[2];
    // d_in[3] = teacher_forcing_ratio (==1; fully teacher-forced, unused)
    const float* pW1 = (const float*)d_in[4];
    const float* pb1 = (const float*)d_in[5];
    const float* pW2 = (const float*)d_in[6];
    const float* pb2 = (const float*)d_in[7];
    const float* aWih = (const float*)d_in[8];
    const float* aWhh = (const float*)d_in[9];
    const float* ab   = (const float*)d_in[10];
    const float* gWih = (const float*)d_in[11];
    const float* gWhh = (const float*)d_in[12];
    const float* gb   = (const float*)d_in[13];
    const float* Wq   = (const float*)d_in[14];
    const float* Wm   = (const float*)d_in[15];
    const float* lk   = (const float*)d_in[16];
    const float* Wloc = (const float*)d_in[17];
    const float* v_att = (const float*)d_in[18];
    const float* b_att = (const float*)d_in[19];
    const float* fW = (const float*)d_in[20];
    const float* fb = (const float*)d_in[21];
    const float* sW = (const float*)d_in[22];
    const float* sb = (const float*)d_in[23];

    float* out  = (float*)d_out;
    float* spec  = out;
    float* stop  = out + (size_t)B_ * TDEC * M_;
    float* align = stop + (size_t)B_ * TDEC;

    const int smem_bytes = POOLFL * 4;   // 168960
    static int configured = 0;
    if (!configured) {
        cudaFuncSetAttribute(decoder_kernel, cudaFuncAttributeMaxDynamicSharedMemorySize, smem_bytes);
        configured = 1;
    }

    init_kernel<<<128, 256>>>();
    prenet_kernel<<<B_ * TDEC, 256>>>(target, pW1, pb1, pW2, pb2);
    procmem_kernel<<<dim3(TENC, B_), 128>>>(enc, Wm);

    decoder_kernel<<<NBLK, NTHR, smem_bytes>>>(enc, lens,
                                               aWih, aWhh, ab, gWih, gWhh, gb,
                                               Wq, lk, Wloc, v_att, b_att,
                                               fW, fb, sW, sb,
                                               spec, stop, align);
}

// round 17
// speedup vs baseline: 1.1288x; 1.1288x over previous
#include <cuda_runtime.h>
#include <math.h>

#define B_    32
#define TENC  200
#define E_    512
#define D_    1024
#define P_    256
#define M_    80
#define TDEC  600
#define A_    128
#define LF_   32
#define KW_   31
#define PADW  15
#define NBLK  128
#define NTHR  512
#define CHUNK 256
#define WPAD  260                 // padded chunk stride in floats (1040B, 16B-aligned)
#define BUFFL (2 * 32 * WPAD)     // floats per (w,x) buffer = 16640
#define REDOFF (2 * BUFFL)        // 33280
#define POOLFL (REDOFF + 8448)    // 41728 floats = 166912 B

// ---------------- device scratch (static, allocation-free) ----------------
__device__ __align__(16) float g_pre[(size_t)B_ * TDEC * P_];
__device__ __align__(16) float g_pm[(size_t)B_ * TENC * A_];
__device__ __align__(16) float g_lp[(size_t)B_ * TENC * A_];
__device__ __align__(16) float g_hatt[B_ * D_];
__device__ __align__(16) float g_catt[B_ * D_];
__device__ __align__(16) float g_hgen[B_ * D_];
__device__ __align__(16) float g_cgen[B_ * D_];
__device__ __align__(16) float g_ctx[2][B_ * E_];
__device__ __align__(16) float g_wprev[B_ * TENC];
__device__ __align__(16) float g_wcum[B_ * TENC];
__device__ __align__(16) float g_gatt[(size_t)B_ * 4 * D_];
__device__ __align__(16) float g_ggen[(size_t)B_ * 4 * D_];

// ---------------- grid barrier ----------------
__device__ unsigned g_count = 0;
__device__ volatile unsigned g_sense = 0;

__device__ __forceinline__ void grid_bar(unsigned& ls) {
    __syncthreads();
    ls ^= 1u;
    if (threadIdx.x == 0) {
        __threadfence();
        unsigned old = atomicAdd(&g_count, 1u);
        if (old == NBLK - 1) {
            atomicExch(&g_count, 0u);
            __threadfence();
            g_sense = ls;
        } else {
            while (g_sense != ls) { __nanosleep(32); }
            __threadfence();
        }
    }
    __syncthreads();
}

// ---------------- helpers ----------------
__device__ __forceinline__ float warp_sum(float v) {
    v += __shfl_xor_sync(0xffffffffu, v, 16);
    v += __shfl_xor_sync(0xffffffffu, v, 8);
    v += __shfl_xor_sync(0xffffffffu, v, 4);
    v += __shfl_xor_sync(0xffffffffu, v, 2);
    v += __shfl_xor_sync(0xffffffffu, v, 1);
    return v;
}
__device__ __forceinline__ float warp_max(float v) {
    v = fmaxf(v, __shfl_xor_sync(0xffffffffu, v, 16));
    v = fmaxf(v, __shfl_xor_sync(0xffffffffu, v, 8));
    v = fmaxf(v, __shfl_xor_sync(0xffffffffu, v, 4));
    v = fmaxf(v, __shfl_xor_sync(0xffffffffu, v, 2));
    v = fmaxf(v, __shfl_xor_sync(0xffffffffu, v, 1));
    return v;
}
__device__ __forceinline__ float sigf(float x) { return 1.f / (1.f + __expf(-x)); }

typedef unsigned long long ull;
__device__ __forceinline__ ull pk(float lo, float hi) {
    ull r; asm("mov.b64 %0, {%1, %2};" : "=l"(r) : "f"(lo), "f"(hi)); return r;
}
__device__ __forceinline__ float2 upk(ull v) {
    float2 f; asm("mov.b64 {%0, %1}, %2;" : "=f"(f.x), "=f"(f.y) : "l"(v)); return f;
}
__device__ __forceinline__ void fma2(ull& acc, ull a, ull b) {
    asm("fma.rn.f32x2 %0, %1, %2, %0;" : "+l"(acc) : "l"(a), "l"(b));
}
__device__ __forceinline__ void lds_2x64(ull& a, ull& b, unsigned saddr) {
    asm volatile("ld.shared.v2.b64 {%0, %1}, [%2];" : "=l"(a), "=l"(b) : "r"(saddr));
}
__device__ __forceinline__ unsigned sptr(const void* p) {
    return (unsigned)__cvta_generic_to_shared(p);
}
__device__ __forceinline__ void cp16(float* smem_dst, const float* gsrc) {
    unsigned s = (unsigned)__cvta_generic_to_shared(smem_dst);
    asm volatile("cp.async.cg.shared.global [%0], [%1], 16;" :: "r"(s), "l"(gsrc));
}
__device__ __forceinline__ void cp_commit() { asm volatile("cp.async.commit_group;"); }
__device__ __forceinline__ void cp_wait0() { asm volatile("cp.async.wait_group 0;"); }

// ---------------- LSTM gate GEMM: gates[b][4096 rows] ----------------
// Block = 32 rows x 32 b. Thread tile 4 rows x 4 b (strided), k-split 8.
// CHUNK=256, two buffers, ONE sync per chunk.
// Race-free ordering (fixes R16): wait0 -> syncthreads -> stage(c+1 into
// buffer (c+1)&1, which held chunk c-1 and is past its compute due to the
// barrier) -> compute c from buffer c&1.
__device__ void lstm_gates(const float* __restrict__ Wih, const float* __restrict__ Whh,
                           int KX,
                           const float* s0, int l0, int st0,
                           const float* s1, int l1, int st1,
                           const float* s2, int st2,
                           float* __restrict__ gates_out, float* pool, int blk) {
    const int KTOT = KX + D_;
    const int NCH = KTOT / CHUNK;
    const int rowbase = blk * 32;
    const int tid = threadIdx.x;
    const int kg = tid >> 6;            // 0..7: K-group of 32 floats within chunk
    const int rg = (tid >> 3) & 7;      // rows {rg + 8i}
    const int bg = tid & 7;             // b {bg + 8j}

    const unsigned pool_sa = sptr(pool);
    float* red = pool + REDOFF;

    // staging: 4096 cp16 per chunk over 512 threads -> 8 per thread
    #define STAGE(buf_, tb_)  do {                                                \
        int tb = (tb_);                                                            \
        float* base_ = pool + (buf_) * BUFFL;                                       \
        _Pragma("unroll")                                                           \
        for (int p_ = 0; p_ < 8; p_++) {                                            \
            int id = p_ * NTHR + tid;                                               \
            int arr = id >> 11;               /* 0 = W, 1 = x */                    \
            int rem = id & 2047;                                                    \
            int row = rem >> 6;                                                     \
            int col = (rem & 63) * 4;                                               \
            int k = tb + col;                                                       \
            const float* src;                                                       \
            if (arr == 0) {                                                         \
                src = (k < KX) ? Wih + (size_t)(rowbase + row) * KX + k             \
                               : Whh + (size_t)(rowbase + row) * D_ + (k - KX);     \
            } else {                                                                \
                if (k < l0)           src = s0 + (size_t)row * st0 + k;             \
                else if (k < l0 + l1) src = s1 + (size_t)row * st1 + (k - l0);      \
                else                  src = s2 + (size_t)row * st2 + (k - l0 - l1); \
            }                                                                       \
            cp16(base_ + (size_t)arr * (32 * WPAD) + row * WPAD + col, src);        \
        }                                                                           \
    } while (0)

    ull acc[4][4];
    #pragma unroll
    for (int i = 0; i < 4; i++)
        #pragma unroll
        for (int j = 0; j < 4; j++) acc[i][j] = 0ull;

    STAGE(0, 0); cp_commit();

    for (int c = 0; c < NCH; c++) {
        cp_wait0();                 // chunk c's copies (committed last iter) complete
        __syncthreads();            // + all threads done computing chunk c-1
        if (c + 1 < NCH) { STAGE((c + 1) & 1, (c + 1) * CHUNK); cp_commit(); }

        const int bi = c & 1;
        const unsigned wbase = pool_sa + (unsigned)(bi * BUFFL + rg * WPAD + kg * 32) * 4u;
        const unsigned xbase = pool_sa + (unsigned)(bi * BUFFL + 32 * WPAD + bg * WPAD + kg * 32) * 4u;
        #pragma unroll
        for (int kk = 0; kk < 8; kk++) {
            ull w[8], x[8];
            lds_2x64(w[0], w[1], wbase + kk * 16);
            lds_2x64(w[2], w[3], wbase + 8 * WPAD * 4 + kk * 16);
            lds_2x64(w[4], w[5], wbase + 16 * WPAD * 4 + kk * 16);
            lds_2x64(w[6], w[7], wbase + 24 * WPAD * 4 + kk * 16);
            lds_2x64(x[0], x[1], xbase + kk * 16);
            lds_2x64(x[2], x[3], xbase + 8 * WPAD * 4 + kk * 16);
            lds_2x64(x[4], x[5], xbase + 16 * WPAD * 4 + kk * 16);
            lds_2x64(x[6], x[7], xbase + 24 * WPAD * 4 + kk * 16);
            #pragma unroll
            for (int i = 0; i < 4; i++)
                #pragma unroll
                for (int j = 0; j < 4; j++) {
                    fma2(acc[i][j], w[2 * i],     x[2 * j]);
                    fma2(acc[i][j], w[2 * i + 1], x[2 * j + 1]);
                }
        }
    }
    #undef STAGE

    __syncthreads();   // all compute done before reusing red region
    #pragma unroll
    for (int i = 0; i < 4; i++)
        #pragma unroll
        for (int j = 0; j < 4; j++) {
            float2 f = upk(acc[i][j]);
            red[kg * (32 * 33) + (rg + 8 * i) * 33 + (bg + 8 * j)] = f.x + f.y;
        }
    __syncthreads();
    for (int p = tid; p < 1024; p += NTHR) {
        int b = p >> 5, r = p & 31;
        float s = 0.f;
        #pragma unroll
        for (int q = 0; q < 8; q++) s += red[q * (32 * 33) + r * 33 + b];
        gates_out[(size_t)b * (4 * D_) + rowbase + r] = s;
    }
    __syncthreads();
}

// ---------------- B1 (blocks 0-31): att pointwise + query ----------------
__device__ void att_pw_query(int b, float* pool,
                             const float* __restrict__ ab,
                             const float* __restrict__ Wq,
                             const float* __restrict__ b_att,
                             const float* __restrict__ v_att) {
    const int tid = threadIdx.x;
    const int warp = tid >> 5, lane = tid & 31;
    float* h_s = pool;           // 1024
    float* q_s = pool + 1024;    // 128
    float* v_s = pool + 1152;    // 128

    const float* gat = g_gatt + (size_t)b * (4 * D_);
    for (int d = tid; d < D_; d += NTHR) {
        float gi = gat[d]          + ab[d];
        float gf = gat[D_ + d]     + ab[D_ + d];
        float gc = gat[2 * D_ + d] + ab[2 * D_ + d];
        float go = gat[3 * D_ + d] + ab[3 * D_ + d];
        float c = sigf(gf) * g_catt[b * D_ + d] + sigf(gi) * tanhf(gc);
        float h = sigf(go) * tanhf(c);
        g_catt[b * D_ + d] = c;
        g_hatt[b * D_ + d] = h;
        h_s[d] = h;
    }
    if (tid < A_) v_s[tid] = v_att[tid];
    __syncthreads();

    const float4* h4 = (const float4*)h_s;
    for (int a = warp * 8; a < warp * 8 + 8; a++) {
        const float4* wq = (const float4*)(Wq + (size_t)a * D_);
        float acc = 0.f;
        #pragma unroll
        for (int kk = 0; kk < 8; kk++) {
            float4 w4 = wq[lane + 32 * kk];
            float4 x4 = h4[lane + 32 * kk];
            acc += w4.x * x4.x + w4.y * x4.y + w4.z * x4.z + w4.w * x4.w;
        }
        acc = warp_sum(acc);
        if (lane == 0) q_s[a] = acc + b_att[a];
    }
    __syncthreads();
}

// ---------------- B1 (blocks 32-127): conv + locproj for (b, third) ----------
__device__ void conv_locproj(int b, int third, float* pool,
                             const float* __restrict__ lk,
                             const float* __restrict__ Wloc) {
    const int tid = threadIdx.x;
    const int lo = third * 67;
    const int n = (third == 2) ? 66 : 67;

    float* wp_s  = pool;          // 104
    float* wc_s  = pool + 104;    // 104
    float* lkT   = pool + 208;    // 62*33
    float* wlocT = pool + 2256;   // 32*129
    float* feat  = pool + 6400;   // 67*36

    for (int idx = tid; idx < 104; idx += NTHR) {
        int j = lo - 15 + idx;
        bool ok = (j >= 0 && j < TENC);
        wp_s[idx] = ok ? g_wprev[b * TENC + j] : 0.f;
        wc_s[idx] = ok ? g_wcum[b * TENC + j] : 0.f;
    }
    for (int idx = tid; idx < 62 * 32; idx += NTHR) {
        int tap = idx >> 5, c = idx & 31;
        lkT[tap * 33 + c] = lk[c * 62 + tap];
    }
    for (int idx = tid; idx < A_ * LF_; idx += NTHR) {
        int a = idx >> 5, c = idx & 31;
        wlocT[c * 129 + a] = Wloc[idx];
    }
    __syncthreads();

    {
        int c = tid & 31, iq = tid >> 5;
        for (int p = 0; p < 2; p++) {
            int ig4 = p * 64 + iq * 4;
            if (ig4 < n) {
                float f0 = 0.f, f1 = 0.f, f2 = 0.f, f3 = 0.f;
                {
                    float a0 = wp_s[ig4], a1 = wp_s[ig4 + 1], a2 = wp_s[ig4 + 2], a3 = wp_s[ig4 + 3];
                    #pragma unroll
                    for (int k = 0; k < KW_; k++) {
                        float lkv = lkT[k * 33 + c];
                        f0 += lkv * a0; f1 += lkv * a1; f2 += lkv * a2; f3 += lkv * a3;
                        a0 = a1; a1 = a2; a2 = a3; a3 = wp_s[ig4 + k + 4];
                    }
                }
                {
                    float a0 = wc_s[ig4], a1 = wc_s[ig4 + 1], a2 = wc_s[ig4 + 2], a3 = wc_s[ig4 + 3];
                    #pragma unroll
                    for (int k = 0; k < KW_; k++) {
                        float lkv = lkT[(KW_ + k) * 33 + c];
                        f0 += lkv * a0; f1 += lkv * a1; f2 += lkv * a2; f3 += lkv * a3;
                        a0 = a1; a1 = a2; a2 = a3; a3 = wc_s[ig4 + k + 4];
                    }
                }
                if (ig4 + 0 < n) feat[(ig4 + 0) * 36 + c] = f0;
                if (ig4 + 1 < n) feat[(ig4 + 1) * 36 + c] = f1;
                if (ig4 + 2 < n) feat[(ig4 + 2) * 36 + c] = f2;
                if (ig4 + 3 < n) feat[(ig4 + 3) * 36 + c] = f3;
            }
        }
    }
    __syncthreads();

    {
        int a = tid & 127, ig2 = tid >> 7;
        ull wl[16];
        #pragma unroll
        for (int p4 = 0; p4 < 8; p4++) {
            wl[2 * p4]     = pk(wlocT[(4 * p4) * 129 + a],     wlocT[(4 * p4 + 1) * 129 + a]);
            wl[2 * p4 + 1] = pk(wlocT[(4 * p4 + 2) * 129 + a], wlocT[(4 * p4 + 3) * 129 + a]);
        }
        unsigned feat_sa = sptr(feat);
        for (int ii = ig2; ii < n; ii += 4) {
            ull acc = 0ull;
            unsigned base = feat_sa + (unsigned)ii * 144u;
            #pragma unroll
            for (int p4 = 0; p4 < 8; p4++) {
                ull f0, f1;
                lds_2x64(f0, f1, base + p4 * 16);
                fma2(acc, wl[2 * p4], f0);
                fma2(acc, wl[2 * p4 + 1], f1);
            }
            float2 f = upk(acc);
            g_lp[((size_t)b * TENC + lo + ii) * A_ + a] = f.x + f.y;
        }
    }
    __syncthreads();
}

// ---------------- B2 (blocks 0-31): energy + softmax + context ----------------
__device__ void energy_softmax_ctx(int b, int t, float* pool,
                                   const int* __restrict__ lens,
                                   const float* __restrict__ enc,
                                   float* __restrict__ align_out) {
    const int tid = threadIdx.x;
    const int warp = tid >> 5, lane = tid & 31;
    float* q_s   = pool + 1024;
    float* v_s   = pool + 1152;
    float* e_s   = pool + 1280;
    float* red16 = pool + 1504;
    float* cpart = pool + 1536;

    int len = lens[b];
    for (int i = warp; i < TENC; i += 16) {
        const float* lp = g_lp + ((size_t)b * TENC + i) * A_;
        const float* pm = g_pm + ((size_t)b * TENC + i) * A_;
        float part = 0.f;
        #pragma unroll
        for (int aa = 0; aa < 4; aa++) {
            int a = aa * 32 + lane;
            part += tanhf(q_s[a] + pm[a] + lp[a]) * v_s[a];
        }
        part = warp_sum(part);
        if (lane == 0) e_s[i] = (i < len) ? part : -1e9f;
    }
    __syncthreads();

    float e = (tid < TENC) ? e_s[tid] : -1e30f;
    float m = warp_max(e);
    if (lane == 0) red16[warp] = m;
    __syncthreads();
    if (tid == 0) {
        float mm = red16[0];
        #pragma unroll
        for (int i = 1; i < 16; i++) mm = fmaxf(mm, red16[i]);
        red16[0] = mm;
    }
    __syncthreads();
    float mx = red16[0];
    __syncthreads();
    float ex = (tid < TENC) ? __expf(e - mx) : 0.f;
    float ssum = warp_sum(ex);
    if (lane == 0) red16[warp] = ssum;
    __syncthreads();
    if (tid == 0) {
        float tot = 0.f;
        #pragma unroll
        for (int i = 0; i < 16; i++) tot += red16[i];
        red16[0] = tot;
    }
    __syncthreads();
    float inv = 1.f / red16[0];
    if (tid < TENC) {
        float w = ex * inv;
        e_s[tid] = w;
        g_wprev[b * TENC + tid] = w;
        g_wcum[b * TENC + tid] += w;
        align_out[((size_t)b * TDEC + t) * TENC + tid] = w;
    }
    __syncthreads();

    if (tid < 256) {
        int col = tid & 127, half = tid >> 7;
        const float4* encb = (const float4*)(enc + (size_t)b * TENC * E_) + col;
        float4 acc = make_float4(0.f, 0.f, 0.f, 0.f);
        #pragma unroll 4
        for (int i = half * 100; i < half * 100 + 100; i++) {
            float w = e_s[i];
            float4 v = encb[(size_t)i * 128];
            acc.x += w * v.x; acc.y += w * v.y; acc.z += w * v.z; acc.w += w * v.w;
        }
        ((float4*)cpart)[tid] = acc;
    }
    __syncthreads();
    if (tid < 128) {
        float4 a0 = ((float4*)cpart)[tid];
        float4 a1 = ((float4*)cpart)[tid + 128];
        float4 r = make_float4(a0.x + a1.x, a0.y + a1.y, a0.z + a1.z, a0.w + a1.w);
        ((float4*)(g_ctx[t & 1] + b * E_))[tid] = r;
    }
    __syncthreads();
}

// ---------------- gen pointwise + frame/stop for step tt ----------------
__device__ void genpw_frame(int b, int tt, float* pool,
                            const float* __restrict__ gb,
                            const float* __restrict__ fW, const float* __restrict__ fb,
                            const float* __restrict__ sW, const float* __restrict__ sb,
                            float* __restrict__ spec, float* __restrict__ stop) {
    const int tid = threadIdx.x;
    const int warp = tid >> 5, lane = tid & 31;
    float* proto = pool;

    const float* gg = g_ggen + (size_t)b * (4 * D_);
    for (int d = tid; d < D_; d += NTHR) {
        float gi = gg[d]          + gb[d];
        float gf = gg[D_ + d]     + gb[D_ + d];
        float gc = gg[2 * D_ + d] + gb[2 * D_ + d];
        float go = gg[3 * D_ + d] + gb[3 * D_ + d];
        float c = sigf(gf) * g_cgen[b * D_ + d] + sigf(gi) * tanhf(gc);
        float h = sigf(go) * tanhf(c);
        g_cgen[b * D_ + d] = c;
        g_hgen[b * D_ + d] = h;
        proto[d] = h;
    }
    const float* cx = g_ctx[tt & 1] + b * E_;
    for (int k = tid; k < E_; k += NTHR) proto[D_ + k] = cx[k];
    __syncthreads();

    for (int r = warp; r < M_ + 1; r += 16) {
        const float* w = (r < M_) ? (fW + (size_t)r * (D_ + E_)) : sW;
        float acc = 0.f;
        for (int k = lane * 4; k < D_ + E_; k += 128) {
            float4 w4 = *(const float4*)(w + k);
            float4 x4 = *(const float4*)(proto + k);
            acc += w4.x * x4.x + w4.y * x4.y + w4.z * x4.z + w4.w * x4.w;
        }
        acc = warp_sum(acc);
        if (lane == 0) {
            if (r < M_) spec[((size_t)b * TDEC + tt) * M_ + r] = acc + fb[r];
            else        stop[(size_t)b * TDEC + tt] = acc + sb[0];
        }
    }
    __syncthreads();
}

// ---------------- the persistent decoder ----------------
__global__ void __launch_bounds__(NTHR, 1)
decoder_kernel(const float* __restrict__ enc, const int* __restrict__ lens,
               const float* __restrict__ aWih, const float* __restrict__ aWhh, const float* __restrict__ ab,
               const float* __restrict__ gWih, const float* __restrict__ gWhh, const float* __restrict__ gb,
               const float* __restrict__ Wq, const float* __restrict__ lk,
               const float* __restrict__ Wloc, const float* __restrict__ v_att, const float* __restrict__ b_att,
               const float* __restrict__ fW, const float* __restrict__ fb,
               const float* __restrict__ sW, const float* __restrict__ sb,
               float* __restrict__ spec, float* __restrict__ stop, float* __restrict__ align_out) {
    extern __shared__ __align__(16) float pool[];
    const int blk = blockIdx.x;
    unsigned ls = g_sense;

    for (int t = 0; t < TDEC; t++) {
        // Phase A: att-LSTM gates. x = [pre_t | ctx_{t-1}], h = h_att^{t-1}
        lstm_gates(aWih, aWhh, P_ + E_,
                   g_pre + (size_t)t * P_, P_, TDEC * P_,
                   g_ctx[(t + 1) & 1], E_, E_,
                   g_hatt, D_,
                   g_gatt, pool, blk);
        grid_bar(ls);
        // Phase B1: pointwise+query (0-31) || conv+locproj (32-127)
        if (blk < 32) {
            att_pw_query(blk, pool, ab, Wq, b_att, v_att);
        } else {
            int cb = blk - 32;
            conv_locproj(cb & 31, cb >> 5, pool, lk, Wloc);
        }
        grid_bar(ls);
        // Phase B2: energy/softmax/context (0-31) || frame of t-1 (32-63)
        if (blk < 32) {
            energy_softmax_ctx(blk, t, pool, lens, enc, align_out);
        } else if (blk < 64 && t > 0) {
            genpw_frame(blk - 32, t - 1, pool, gb, fW, fb, sW, sb, spec, stop);
        }
        grid_bar(ls);
        // Phase C: gen-LSTM gates. x = [h_att | ctx_t], h = h_gen^{t-1}
        lstm_gates(gWih, gWhh, D_ + E_,
                   g_hatt, D_, D_,
                   g_ctx[t & 1], E_, E_,
                   g_hgen, D_,
                   g_ggen, pool, blk);
    }
    grid_bar(ls);
    if (blk >= 32 && blk < 64) {
        genpw_frame(blk - 32, TDEC - 1, pool, gb, fW, fb, sW, sb, spec, stop);
    }
}

// ---------------- prologue kernels ----------------
__global__ void init_kernel() {
    int i = blockIdx.x * blockDim.x + threadIdx.x;
    if (i < B_ * D_) { g_hatt[i] = 0.f; g_catt[i] = 0.f; g_hgen[i] = 0.f; g_cgen[i] = 0.f; }
    if (i < B_ * E_) { g_ctx[0][i] = 0.f; g_ctx[1][i] = 0.f; }
    if (i < B_ * TENC) { g_wprev[i] = 0.f; g_wcum[i] = 0.f; }
}

__global__ void prenet_kernel(const float* __restrict__ target,
                              const float* __restrict__ W1, const float* __restrict__ b1,
                              const float* __restrict__ W2, const float* __restrict__ b2) {
    int bt = blockIdx.x;
    int b = bt / TDEC, t = bt % TDEC;
    __shared__ float st[M_];
    __shared__ float sx1[P_];
    int tid = threadIdx.x;  // 256
    int warp = tid >> 5, lane = tid & 31;
    if (tid < M_) st[tid] = (t == 0) ? 0.f : target[((size_t)b * M_ + tid) * TDEC + (t - 1)];
    __syncthreads();
    for (int j = 0; j < 32; j++) {
        int p = warp * 32 + j;
        const float* w = W1 + (size_t)p * M_;
        float acc = w[lane] * st[lane] + w[lane + 32] * st[lane + 32];
        if (lane < 16) acc += w[lane + 64] * st[lane + 64];
        acc = warp_sum(acc);
        if (lane == 0) sx1[p] = fmaxf(acc + b1[p], 0.f);
    }
    __syncthreads();
    for (int j = 0; j < 32; j++) {
        int p = warp * 32 + j;
        const float* w = W2 + (size_t)p * P_;
        float acc = 0.f;
        #pragma unroll
        for (int q = 0; q < 8; q++) acc += w[lane + 32 * q] * sx1[lane + 32 * q];
        acc = warp_sum(acc);
        if (lane == 0) g_pre[((size_t)b * TDEC + t) * P_ + p] = fmaxf(acc + b2[p], 0.f);
    }
}

__global__ void procmem_kernel(const float* __restrict__ enc, const float* __restrict__ Wm) {
    int i = blockIdx.x, b = blockIdx.y;
    __shared__ __align__(16) float se[E_];
    int tid = threadIdx.x;  // 128
    int warp = tid >> 5, lane = tid & 31;
    for (int k = tid; k < E_; k += 128) se[k] = enc[((size_t)b * TENC + i) * E_ + k];
    __syncthreads();
    const float4* se4 = (const float4*)se;
    for (int j = 0; j < 32; j++) {
        int a = warp * 32 + j;
        const float4* w4 = (const float4*)(Wm + (size_t)a * E_);
        float acc = 0.f;
        #pragma unroll
        for (int q = 0; q < 4; q++) {
            float4 w = w4[lane + 32 * q];
            float4 x = se4[lane + 32 * q];
            acc += w.x * x.x + w.y * x.y + w.z * x.z + w.w * x.w;
        }
        acc = warp_sum(acc);
        if (lane == 0) g_pm[((size_t)b * TENC + i) * A_ + a] = acc;
    }
}

// ---------------- launch ----------------
extern "C" void kernel_launch(void* const* d_in, const int* in_sizes, int n_in,
                              void* d_out, int out_size) {
    const float* enc    = (const float*)d_in[0];
    const int*   lens   = (const int*)d_in[1];
    const float* target = (const float*)d_in[2];
    // d_in[3] = teacher_forcing_ratio (==1; fully teacher-forced, unused)
    const float* pW1 = (const float*)d_in[4];
    const float* pb1 = (const float*)d_in[5];
    const float* pW2 = (const float*)d_in[6];
    const float* pb2 = (const float*)d_in[7];
    const float* aWih = (const float*)d_in[8];
    const float* aWhh = (const float*)d_in[9];
    const float* ab   = (const float*)d_in[10];
    const float* gWih = (const float*)d_in[11];
    const float* gWhh = (const float*)d_in[12];
    const float* gb   = (const float*)d_in[13];
    const float* Wq   = (const float*)d_in[14];
    const float* Wm   = (const float*)d_in[15];
    const float* lk   = (const float*)d_in[16];
    const float* Wloc = (const float*)d_in[17];
    const float* v_att = (const float*)d_in[18];
    const float* b_att = (const float*)d_in[19];
    const float* fW = (const float*)d_in[20];
    const float* fb = (const float*)d_in[21];
    const float* sW = (const float*)d_in[22];
    const float* sb = (const float*)d_in[23];

    float* out  = (float*)d_out;
    float* spec  = out;
    float* stop  = out + (size_t)B_ * TDEC * M_;
    float* align = stop + (size_t)B_ * TDEC;

    const int smem_bytes = POOLFL * 4;   // 166912
    static int configured = 0;
    if (!configured) {
        cudaFuncSetAttribute(decoder_kernel, cudaFuncAttributeMaxDynamicSharedMemorySize, smem_bytes);
        configured = 1;
    }

    init_kernel<<<128, 256>>>();
    prenet_kernel<<<B_ * TDEC, 256>>>(target, pW1, pb1, pW2, pb2);
    procmem_kernel<<<dim3(TENC, B_), 128>>>(enc, Wm);

    decoder_kernel<<<NBLK, NTHR, smem_bytes>>>(enc, lens,
                                               aWih, aWhh, ab, gWih, gWhh, gb,
                                               Wq, lk, Wloc, v_att, b_att,
                                               fW, fb, sW, sb,
                                               spec, stop, align);
}